// round 7
// baseline (speedup 1.0000x reference)
#include <cuda_runtime.h>
#include <math.h>
#include <stdint.h>

#define BZ   8
#define IM   128
#define HW   (IM * IM)          // 16384
#define CIN  3

// dft_gemm dynamic smem layout (bytes):
//   [0,      65536)  sW4  : float4[32*128]  swizzled W
//   [65536,  67584)  sRe  : float[4][128]
//   [67584,  69632)  sIm  : float[4][128]
//   [69632,  71680)  sS   : float[4][128]
//   [71680,  72192)  t128c: float[128]
//   [72192,  72704)  t128s: float[128]
//   [72704,  72832)  t32c : float[32]
//   [72832,  72960)  t32s : float[32]
#define SMEM_BYTES_DFT 72960

// Scratch: E[b][o][w] = leakyrelu(W @ S)
__device__ float g_E[BZ * IM * IM];

// ---------------------------------------------------------------------------
// K1: fused radix-4 column DFT magnitude + 1x1-conv GEMM + LeakyReLU.
// One batch per launch. grid = 32 col-groups, block = 128 = 4 warps = 4 cols.
// ---------------------------------------------------------------------------
__global__ void __launch_bounds__(128) dft_gemm_kernel(const float* __restrict__ x,
                                                       const float* __restrict__ conv_w,
                                                       int b) {
    extern __shared__ char smem[];
    float4* sW4   = (float4*)(smem);
    float (*sRe)[IM] = (float (*)[IM])(smem + 65536);
    float (*sIm)[IM] = (float (*)[IM])(smem + 67584);
    float (*sS )[IM] = (float (*)[IM])(smem + 69632);
    float* t128c = (float*)(smem + 71680);
    float* t128s = (float*)(smem + 72192);
    float* t32c  = (float*)(smem + 72704);
    float* t32s  = (float*)(smem + 72832);

    const int w0   = blockIdx.x * 4;
    const int tid  = threadIdx.x;
    const int wl   = tid >> 5;
    const int lane = tid & 31;

    // Stage W: coalesced loads, swizzled stores.  o = row, j = float4-in-row.
    const float4* W4 = (const float4*)conv_w;
#pragma unroll
    for (int it = 0; it < 32; it++) {
        int idx = tid + 128 * it;                      // 0..4095
        int o = idx >> 5, j = idx & 31;
        sW4[j * IM + (j ^ o)] = W4[o * 32 + j];
    }

    // Load 4 columns (both channels) as float4 rows.
    const float* xb = x + (size_t)b * CIN * HW;
    for (int k = tid; k < 256; k += 128) {
        int ch = k >> 7, h = k & 127;
        float4 v = ((const float4*)(xb + (size_t)ch * HW))[h * (IM / 4) + (w0 >> 2)];
        float (*dst)[IM] = ch ? sIm : sRe;
        dst[0][h] = v.x; dst[1][h] = v.y; dst[2][h] = v.z; dst[3][h] = v.w;
    }

    // Twiddle tables (exact, one sincosf per thread).
    {
        float s, c;
        sincosf(-6.283185307179586f * (float)tid * (1.0f / 128.0f), &s, &c);
        t128c[tid] = c; t128s[tid] = s;
        if (tid < 32) {
            sincosf(-6.283185307179586f * (float)tid * (1.0f / 32.0f), &s, &c);
            t32c[tid] = c; t32s[tid] = s;
        }
    }
    __syncthreads();

    // Radix-4 DFT: 4 phase accumulators, table twiddles.
    float A0r = 0, A0i = 0, A1r = 0, A1i = 0, A2r = 0, A2i = 0, A3r = 0, A3i = 0;
    const float4* r4 = (const float4*)sRe[wl];
    const float4* m4 = (const float4*)sIm[wl];

#pragma unroll
    for (int t = 0; t < 32; t++) {
        int   k = (lane * t) & 31;
        float c = t32c[k], s = t32s[k];
        float4 xr = r4[t];
        float4 xm = m4[t];
        A0r = fmaf(xr.x, c, A0r); A0r = fmaf(-xm.x, s, A0r);
        A0i = fmaf(xr.x, s, A0i); A0i = fmaf( xm.x, c, A0i);
        A1r = fmaf(xr.y, c, A1r); A1r = fmaf(-xm.y, s, A1r);
        A1i = fmaf(xr.y, s, A1i); A1i = fmaf( xm.y, c, A1i);
        A2r = fmaf(xr.z, c, A2r); A2r = fmaf(-xm.z, s, A2r);
        A2i = fmaf(xr.z, s, A2i); A2i = fmaf( xm.z, c, A2i);
        A3r = fmaf(xr.w, c, A3r); A3r = fmaf(-xm.w, s, A3r);
        A3i = fmaf(xr.w, s, A3i); A3i = fmaf( xm.w, c, A3i);
    }

    // Final twiddles W^lane, W^2lane, W^3lane (exact table reads).
    float cw = t128c[lane],             sw = t128s[lane];
    float c2 = t128c[(2 * lane) & 127], s2 = t128s[(2 * lane) & 127];
    float c3 = t128c[(3 * lane) & 127], s3 = t128s[(3 * lane) & 127];

    float T0r = A0r,                 T0i = A0i;
    float T1r = cw * A1r - sw * A1i, T1i = cw * A1i + sw * A1r;
    float T2r = c2 * A2r - s2 * A2i, T2i = c2 * A2i + s2 * A2r;
    float T3r = c3 * A3r - s3 * A3i, T3i = c3 * A3i + s3 * A3r;

    float Er = T0r + T2r, Ei = T0i + T2i;
    float Fr = T1r + T3r, Fi = T1i + T3i;
    float Gr = T0r - T2r, Gi = T0i - T2i;
    float Hr = T1r - T3r, Hi = T1i - T3i;

    float m0r = Er + Fr, m0i = Ei + Fi;
    float m2r = Er - Fr, m2i = Ei - Fi;
    float m1r = Gr + Hi, m1i = Gi - Hr;
    float m3r = Gr - Hi, m3i = Gi + Hr;

    const float inv = 1.0f / 128.0f;
    sS[wl][lane     ] = sqrtf(m0r * m0r + m0i * m0i) * inv;
    sS[wl][lane + 32] = sqrtf(m1r * m1r + m1i * m1i) * inv;
    sS[wl][lane + 64] = sqrtf(m2r * m2r + m2i * m2i) * inv;
    sS[wl][lane + 96] = sqrtf(m3r * m3r + m3i * m3i) * inv;
    __syncthreads();

    // GEMM: thread t = output channel o; 4 w-accumulators.
    float a0 = 0, a1 = 0, a2 = 0, a3 = 0;
    const float4* q0 = (const float4*)sS[0];
    const float4* q1 = (const float4*)sS[1];
    const float4* q2 = (const float4*)sS[2];
    const float4* q3 = (const float4*)sS[3];

#pragma unroll 8
    for (int i4 = 0; i4 < 32; i4++) {
        float4 wv = sW4[i4 * IM + (i4 ^ tid)];         // conflict-free swizzled read
        float4 v0 = q0[i4], v1 = q1[i4], v2 = q2[i4], v3 = q3[i4];
        a0 = fmaf(wv.x, v0.x, a0); a0 = fmaf(wv.y, v0.y, a0);
        a0 = fmaf(wv.z, v0.z, a0); a0 = fmaf(wv.w, v0.w, a0);
        a1 = fmaf(wv.x, v1.x, a1); a1 = fmaf(wv.y, v1.y, a1);
        a1 = fmaf(wv.z, v1.z, a1); a1 = fmaf(wv.w, v1.w, a1);
        a2 = fmaf(wv.x, v2.x, a2); a2 = fmaf(wv.y, v2.y, a2);
        a2 = fmaf(wv.z, v2.z, a2); a2 = fmaf(wv.w, v2.w, a2);
        a3 = fmaf(wv.x, v3.x, a3); a3 = fmaf(wv.y, v3.y, a3);
        a3 = fmaf(wv.z, v3.z, a3); a3 = fmaf(wv.w, v3.w, a3);
    }

    float4 e;
    e.x = (a0 >= 0.0f) ? a0 : 0.2f * a0;
    e.y = (a1 >= 0.0f) ? a1 : 0.2f * a1;
    e.z = (a2 >= 0.0f) ? a2 : 0.2f * a2;
    e.w = (a3 >= 0.0f) ? a3 : 0.2f * a3;
    *(float4*)(g_E + (size_t)(b * IM + tid) * IM + w0) = e;
}

// ---------------------------------------------------------------------------
// K2: broadcast E over h into out, one batch per launch.
// grid = 128 (o), block = 256. Pure register-resident STG.128 streams.
// ---------------------------------------------------------------------------
__global__ void __launch_bounds__(256) bcast_kernel(float* __restrict__ out, int b) {
    const int o   = blockIdx.x;    // 0..127
    const int tid = threadIdx.x;

    float4* out4 = (float4*)(out + (size_t)(b * (IM + 1) + o) * HW);
    const float4* e4 = (const float4*)(g_E + (size_t)(b * IM + o) * IM);
    float4 v = e4[tid & 31];           // register-resident row chunk
    const int w4 = tid & 31;
    const int h0 = tid >> 5;           // 0..7
#pragma unroll
    for (int h = h0; h < IM; h += 8) out4[h * (IM / 4) + w4] = v;
}

// ---------------------------------------------------------------------------
// K3: passthrough of channel 2 for all batches (independent of DFT chain).
// grid = 8 (b), block = 256.
// ---------------------------------------------------------------------------
__global__ void __launch_bounds__(256) pass_kernel(const float* __restrict__ x,
                                                   float* __restrict__ out) {
    const int b   = blockIdx.x;
    const int tid = threadIdx.x;
    float4*       d4  = (float4*)(out + (size_t)(b * (IM + 1) + IM) * HW);
    const float4* src = (const float4*)(x + (size_t)b * CIN * HW + 2 * HW);
#pragma unroll
    for (int j = tid; j < HW / 4; j += 256) d4[j] = src[j];
}

// ---------------------------------------------------------------------------
extern "C" void kernel_launch(void* const* d_in, const int* in_sizes, int n_in,
                              void* d_out, int out_size) {
    const float* x      = (const float*)d_in[0];
    const float* conv_w = (const float*)d_in[2];
    float*       out    = (float*)d_out;

    cudaFuncSetAttribute(dft_gemm_kernel,
                         cudaFuncAttributeMaxDynamicSharedMemorySize, SMEM_BYTES_DFT);

    // Fork a second stream off the (captured) main stream so bcast(b) overlaps
    // dft(b+1). Streams/events are intentionally NOT destroyed here: destroying
    // capture-participating objects before capture ends can invalidate the
    // graph; a few leaked host handles across the harness's calls are harmless.
    cudaStream_t s1;
    cudaStreamCreate(&s1);
    cudaEvent_t evF, evJ, evD[BZ];
    cudaEventCreateWithFlags(&evF, cudaEventDisableTiming);
    cudaEventCreateWithFlags(&evJ, cudaEventDisableTiming);
    for (int b = 0; b < BZ; b++)
        cudaEventCreateWithFlags(&evD[b], cudaEventDisableTiming);

    // fork
    cudaEventRecord(evF, 0);
    cudaStreamWaitEvent(s1, evF, 0);

    // independent passthrough runs on the forked stream immediately
    pass_kernel<<<BZ, 256, 0, s1>>>(x, out);

    // per-batch pipeline: dft(b) on main, bcast(b) on s1 after event
    for (int b = 0; b < BZ; b++) {
        dft_gemm_kernel<<<32, 128, SMEM_BYTES_DFT, 0>>>(x, conv_w, b);
        cudaEventRecord(evD[b], 0);
        cudaStreamWaitEvent(s1, evD[b], 0);
        bcast_kernel<<<IM, 256, 0, s1>>>(out, b);
    }

    // join back to the main (captured) stream
    cudaEventRecord(evJ, s1);
    cudaStreamWaitEvent(0, evJ, 0);
}

// round 8
// speedup vs baseline: 2.8250x; 2.8250x over previous
#include <cuda_runtime.h>
#include <math.h>
#include <stdint.h>

#define BZ   8
#define IM   128
#define HW   (IM * IM)          // 16384
#define CIN  3

// dft_gemm dynamic smem layout (bytes):
//   [0,      32768)  sW4  : float4[32*64]   swizzled half-W (64 o-rows)
//   [32768,  34816)  sRe  : float[4][128]
//   [34816,  36864)  sIm  : float[4][128]
//   [36864,  38912)  sS   : float[4][128]
//   [38912,  39424)  t128c: float[128]
//   [39424,  39936)  t128s: float[128]
//   [39936,  40064)  t32c : float[32]
//   [40064,  40192)  t32s : float[32]
#define SMEM_BYTES_DFT 40192

// Scratch: E[b][o][w] = leakyrelu(W @ S)
__device__ float g_E[BZ * IM * IM];

// ---------------------------------------------------------------------------
// K1: fused radix-4 column DFT magnitude + half-W GEMM + LeakyReLU.
// grid = (32 col-groups, 2 o-halves, 8 b), block = 128 = 4 warps = 4 columns.
// Each block: DFT for 4 columns (duplicated across o-halves, cheap), then
// GEMM for 64 output channels x 4 w (thread: o = tid&63, two w's).
// ---------------------------------------------------------------------------
__global__ void __launch_bounds__(128) dft_gemm_kernel(const float* __restrict__ x,
                                                       const float* __restrict__ conv_w) {
    extern __shared__ char smem[];
    float4* sW4   = (float4*)(smem);                      // [j][o'] swizzled
    float (*sRe)[IM] = (float (*)[IM])(smem + 32768);
    float (*sIm)[IM] = (float (*)[IM])(smem + 34816);
    float (*sS )[IM] = (float (*)[IM])(smem + 36864);
    float* t128c = (float*)(smem + 38912);
    float* t128s = (float*)(smem + 39424);
    float* t32c  = (float*)(smem + 39936);
    float* t32s  = (float*)(smem + 40064);

    const int w0   = blockIdx.x * 4;
    const int og   = blockIdx.y;          // 0/1 : o in [og*64, og*64+64)
    const int b    = blockIdx.z;
    const int tid  = threadIdx.x;
    const int wl   = tid >> 5;
    const int lane = tid & 31;

    // Stage half of W: rows [og*64, og*64+64). 2048 float4, 16 per thread.
    // Coalesced loads; swizzled stores sW4[j*64 + (j^o')] (j<32, o'<64 -> in range).
    const float4* W4 = (const float4*)conv_w;
#pragma unroll
    for (int it = 0; it < 16; it++) {
        int idx = tid + 128 * it;                          // 0..2047
        int op = idx >> 5, j = idx & 31;                   // o' in [0,64), j in [0,32)
        sW4[j * 64 + (j ^ op)] = W4[(og * 64 + op) * 32 + j];
    }

    // Load 4 columns (both channels) as float4 rows.
    const float* xb = x + (size_t)b * CIN * HW;
    for (int k = tid; k < 256; k += 128) {
        int ch = k >> 7, h = k & 127;
        float4 v = ((const float4*)(xb + (size_t)ch * HW))[h * (IM / 4) + (w0 >> 2)];
        float (*dst)[IM] = ch ? sIm : sRe;
        dst[0][h] = v.x; dst[1][h] = v.y; dst[2][h] = v.z; dst[3][h] = v.w;
    }

    // Twiddle tables (exact, one sincosf per thread).
    {
        float s, c;
        sincosf(-6.283185307179586f * (float)tid * (1.0f / 128.0f), &s, &c);
        t128c[tid] = c; t128s[tid] = s;
        if (tid < 32) {
            sincosf(-6.283185307179586f * (float)tid * (1.0f / 32.0f), &s, &c);
            t32c[tid] = c; t32s[tid] = s;
        }
    }
    __syncthreads();

    // Radix-4 DFT: lane i -> outputs i, i+32, i+64, i+96 of its warp's column.
    float A0r = 0, A0i = 0, A1r = 0, A1i = 0, A2r = 0, A2i = 0, A3r = 0, A3i = 0;
    const float4* r4 = (const float4*)sRe[wl];
    const float4* m4 = (const float4*)sIm[wl];

#pragma unroll
    for (int t = 0; t < 32; t++) {
        int   k = (lane * t) & 31;
        float c = t32c[k], s = t32s[k];
        float4 xr = r4[t];
        float4 xm = m4[t];
        A0r = fmaf(xr.x, c, A0r); A0r = fmaf(-xm.x, s, A0r);
        A0i = fmaf(xr.x, s, A0i); A0i = fmaf( xm.x, c, A0i);
        A1r = fmaf(xr.y, c, A1r); A1r = fmaf(-xm.y, s, A1r);
        A1i = fmaf(xr.y, s, A1i); A1i = fmaf( xm.y, c, A1i);
        A2r = fmaf(xr.z, c, A2r); A2r = fmaf(-xm.z, s, A2r);
        A2i = fmaf(xr.z, s, A2i); A2i = fmaf( xm.z, c, A2i);
        A3r = fmaf(xr.w, c, A3r); A3r = fmaf(-xm.w, s, A3r);
        A3i = fmaf(xr.w, s, A3i); A3i = fmaf( xm.w, c, A3i);
    }

    float cw = t128c[lane],             sw = t128s[lane];
    float c2 = t128c[(2 * lane) & 127], s2 = t128s[(2 * lane) & 127];
    float c3 = t128c[(3 * lane) & 127], s3 = t128s[(3 * lane) & 127];

    float T0r = A0r,                 T0i = A0i;
    float T1r = cw * A1r - sw * A1i, T1i = cw * A1i + sw * A1r;
    float T2r = c2 * A2r - s2 * A2i, T2i = c2 * A2i + s2 * A2r;
    float T3r = c3 * A3r - s3 * A3i, T3i = c3 * A3i + s3 * A3r;

    float Er = T0r + T2r, Ei = T0i + T2i;
    float Fr = T1r + T3r, Fi = T1i + T3i;
    float Gr = T0r - T2r, Gi = T0i - T2i;
    float Hr = T1r - T3r, Hi = T1i - T3i;

    float m0r = Er + Fr, m0i = Ei + Fi;
    float m2r = Er - Fr, m2i = Ei - Fi;
    float m1r = Gr + Hi, m1i = Gi - Hr;
    float m3r = Gr - Hi, m3i = Gi + Hr;

    const float inv = 1.0f / 128.0f;
    sS[wl][lane     ] = sqrtf(m0r * m0r + m0i * m0i) * inv;
    sS[wl][lane + 32] = sqrtf(m1r * m1r + m1i * m1i) * inv;
    sS[wl][lane + 64] = sqrtf(m2r * m2r + m2i * m2i) * inv;
    sS[wl][lane + 96] = sqrtf(m3r * m3r + m3i * m3i) * inv;
    __syncthreads();

    // GEMM: thread -> (o = og*64 + (tid&63), two w's selected by half = tid>>6).
    const int op   = tid & 63;
    const int half = tid >> 6;
    float a0 = 0, a1 = 0;
    const float4* qa = (const float4*)sS[2 * half];
    const float4* qb = (const float4*)sS[2 * half + 1];

#pragma unroll 8
    for (int i4 = 0; i4 < 32; i4++) {
        float4 wv = sW4[i4 * 64 + (i4 ^ op)];              // conflict-free
        float4 va = qa[i4], vb = qb[i4];
        a0 = fmaf(wv.x, va.x, a0); a0 = fmaf(wv.y, va.y, a0);
        a0 = fmaf(wv.z, va.z, a0); a0 = fmaf(wv.w, va.w, a0);
        a1 = fmaf(wv.x, vb.x, a1); a1 = fmaf(wv.y, vb.y, a1);
        a1 = fmaf(wv.z, vb.z, a1); a1 = fmaf(wv.w, vb.w, a1);
    }

    float2 e;
    e.x = (a0 >= 0.0f) ? a0 : 0.2f * a0;
    e.y = (a1 >= 0.0f) ? a1 : 0.2f * a1;
    *(float2*)(g_E + (size_t)(b * IM + og * 64 + op) * IM + w0 + 2 * half) = e;
}

// ---------------------------------------------------------------------------
// K2: broadcast E over h into out; o==128 copies x channel 2.
// grid = (129 o, 8 b), block = 256 threads. (R5-proven form.)
// ---------------------------------------------------------------------------
__global__ void __launch_bounds__(256) bcast_kernel(const float* __restrict__ x,
                                                    float* __restrict__ out) {
    const int o   = blockIdx.x;    // 0..128
    const int b   = blockIdx.y;
    const int tid = threadIdx.x;

    float4* out4 = (float4*)(out + (size_t)(b * (IM + 1) + o) * HW);

    if (o == IM) {
        const float4* src = (const float4*)(x + (size_t)b * CIN * HW + 2 * HW);
#pragma unroll
        for (int j = tid; j < HW / 4; j += 256) out4[j] = src[j];
        return;
    }

    const float4* e4 = (const float4*)(g_E + (size_t)(b * IM + o) * IM);
    float4 v = e4[tid & 31];           // register-resident row chunk
    const int w4 = tid & 31;
    const int h0 = tid >> 5;           // 0..7
#pragma unroll
    for (int h = h0; h < IM; h += 8) out4[h * (IM / 4) + w4] = v;
}

// ---------------------------------------------------------------------------
extern "C" void kernel_launch(void* const* d_in, const int* in_sizes, int n_in,
                              void* d_out, int out_size) {
    const float* x      = (const float*)d_in[0];
    const float* conv_w = (const float*)d_in[2];
    float*       out    = (float*)d_out;

    cudaFuncSetAttribute(dft_gemm_kernel,
                         cudaFuncAttributeMaxDynamicSharedMemorySize, SMEM_BYTES_DFT);

    dft_gemm_kernel<<<dim3(32, 2, BZ), 128, SMEM_BYTES_DFT>>>(x, conv_w);
    bcast_kernel<<<dim3(IM + 1, BZ), 256>>>(x, out);
}